// round 15
// baseline (speedup 1.0000x reference)
#include <cuda_runtime.h>
#include <cuda_bf16.h>

// StandardDeviationPooling: 4x4 window, stride 2, VALID.
// Input:  [64, 1024, 1024, 1] fp32   Output: [64, 511*511] fp32
// std = sqrt(max(E[x^2] - E[x]^2, 0)) per window.
//
// R15 (final polish): R14 + fast guarded sqrt in the epilogue:
//   std = (v > 0) ? v * rsqrt(v) : 0   (MUFU.RSQ native, ~2^-22 rel acc,
// vs sqrtf's RSQ+Newton+fixup chain). Everything else unchanged from the
// converged R14 build:
//  - boustrophedon strips: strip-boundary re-reads hit L2; DRAM traffic at
//    the ~316 MB floor (256 MB in + 67 MB out, once each).
//  - compile-time strip direction + FULL/TAIL guard specialization.
//  - RPT=14 -> 37 strips * 64 batches = 2368 CTAs = exact 2 waves @ occ 8.
//  - loads: LDG.128 (own 4 cols) + LDG.64 (2-col right overlap) per row.
//  - stores: sector-aligned paired STG.64 __stcs when (b+orow) even.
// Measured R14: 6273 GB/s (78.4% spec) — at the HBM mixed-stream ceiling.

#define H_IN 1024
#define W_IN 1024
#define H_OUT 511
#define W_OUT 511
#define ROWS_PER_THREAD 14
#define NSTRIPS 37           // ceil(511/14); strip 36 is the tail

__device__ __forceinline__ float fast_std(float s, float q) {
    const float inv_n = 1.0f / 16.0f;
    const float m = s * inv_n;
    const float v = fmaf(-m, m, q * inv_n);
    // sqrt(max(v,0)) via v*rsqrt(v); guard v<=0 -> 0 (matches reference clamp)
    return (v > 0.f) ? v * __frsqrt_rn(v) : 0.f;
}

__device__ __forceinline__ void emit_row(
    float* __restrict__ orow_p, int oc0, bool aligned8,
    float s0, float q0, float s1, float q1)
{
    const float v0 = fast_std(s0, q0);
    if (oc0 + 1 < W_OUT) {
        const float v1 = fast_std(s1, q1);
        if (aligned8) {
            // (b + orow) even -> 8B-aligned pair: one full-sector STG.64
            __stcs(reinterpret_cast<float2*>(orow_p + oc0), make_float2(v0, v1));
        } else {
            __stcs(orow_p + oc0, v0);
            __stcs(orow_p + oc0 + 1, v1);
        }
    } else {
        __stcs(orow_p + oc0, v0);   // c == 255: single trailing column
    }
}

template<bool ASC, bool FULL>
__device__ __forceinline__ void run_strip(
    const float* __restrict__ inb, float* __restrict__ outb,
    int r0, int ic, int oc0, bool has2, int b)
{
    float ps0 = 0.f, ps1 = 0.f, pq0 = 0.f, pq1 = 0.f;

    #pragma unroll
    for (int t = 0; t <= ROWS_PER_THREAD; ++t) {
        const int p    = ASC ? t : (ROWS_PER_THREAD - t);   // compile-time affine
        const int irow = 2 * (r0 + p);
        float cs0 = 0.f, cs1 = 0.f, cq0 = 0.f, cq1 = 0.f;

        if (FULL || (irow + 1 < H_IN)) {
            #pragma unroll
            for (int rr = 0; rr < 2; ++rr) {
                const float* rowp = inb + (size_t)(irow + rr) * W_IN + ic;
                const float4 a = *reinterpret_cast<const float4*>(rowp);
                float2 d;
                if (has2) d = *reinterpret_cast<const float2*>(rowp + 4);  // LDG.64
                else      d = make_float2(0.f, 0.f);

                cs0 += a.x + a.y + a.z + a.w;
                cq0 = fmaf(a.x, a.x, fmaf(a.y, a.y, fmaf(a.z, a.z, fmaf(a.w, a.w, cq0))));
                cs1 += a.z + a.w + d.x + d.y;
                cq1 = fmaf(a.z, a.z, fmaf(a.w, a.w, fmaf(d.x, d.x, fmaf(d.y, d.y, cq1))));
            }
        }

        if (t > 0) {
            // ascending: output row uses pairs (p-1, p)  -> orow = r0 + p - 1
            // descending: output row uses pairs (p, p+1) -> orow = r0 + p
            const int orow = ASC ? (r0 + p - 1) : (r0 + p);
            if (FULL || (orow < H_OUT)) {
                float* orow_p = outb + (size_t)orow * W_OUT;
                const bool aligned8 = (((b + orow) & 1) == 0);  // pitch 511 is odd
                emit_row(orow_p, oc0, aligned8,
                         ps0 + cs0, pq0 + cq0, ps1 + cs1, pq1 + cq1);
            }
        }
        ps0 = cs0; ps1 = cs1; pq0 = cq0; pq1 = cq1;
    }
}

__global__ __launch_bounds__(256, 8)
void std_pool_kernel(const float* __restrict__ in, float* __restrict__ out) {
    const int c     = threadIdx.x;                 // col-pair index 0..255
    const int strip = blockIdx.y;
    const int r0    = strip * ROWS_PER_THREAD;
    const int b     = blockIdx.z;

    const float* __restrict__ inb  = in  + (size_t)b * H_IN * W_IN;
    float* __restrict__       outb = out + (size_t)b * H_OUT * W_OUT;

    const int  ic   = 4 * c;                 // first input col
    const bool has2 = (ic + 5) < W_IN;       // float2 at rowp+4 in-bounds (c < 255)
    const int  oc0  = 2 * c;

    const bool full = (strip != NSTRIPS - 1);   // only the last strip needs guards
    if ((strip & 1) == 0) {
        if (full) run_strip<true,  true >(inb, outb, r0, ic, oc0, has2, b);
        else      run_strip<true,  false>(inb, outb, r0, ic, oc0, has2, b);
    } else {
        if (full) run_strip<false, true >(inb, outb, r0, ic, oc0, has2, b);
        else      run_strip<false, false>(inb, outb, r0, ic, oc0, has2, b);
    }
}

extern "C" void kernel_launch(void* const* d_in, const int* in_sizes, int n_in,
                              void* d_out, int out_size) {
    const float* in = (const float*)d_in[0];
    float* out = (float*)d_out;
    (void)in_sizes; (void)n_in; (void)out_size;

    // 256 col-pair threads cover 511 output cols; 37 strips of 14 rows; 64 batches.
    // 37*64 = 2368 CTAs = exactly 2 waves at 8 CTAs/SM x 148 SMs.
    dim3 block(256, 1, 1);
    dim3 grid(1, NSTRIPS, 64);
    std_pool_kernel<<<grid, block>>>(in, out);
}

// round 16
// speedup vs baseline: 1.0121x; 1.0121x over previous
#include <cuda_runtime.h>
#include <cuda_bf16.h>

// StandardDeviationPooling: 4x4 window, stride 2, VALID.
// Input:  [64, 1024, 1024, 1] fp32   Output: [64, 511*511] fp32
// std = sqrt(max(E[x^2] - E[x]^2, 0)) per window.
//
// R16 = R14 verbatim (FINAL, measured session optimum: 50.43us kernel,
// 6273 GB/s = 78.4% of spec, DRAM traffic at the ~316 MB floor).
// R15's hand-rolled rsqrt epilogue regressed (predicate chain serialized the
// store path; issue% 40->55) and is reverted.
//  - boustrophedon strips: strip-boundary re-reads hit L2; each input byte
//    read from DRAM exactly once, each output byte written once.
//  - compile-time strip direction + FULL/TAIL guard specialization
//    (guard-free body for 36 of 37 strips).
//  - RPT=14 -> 37 strips * 64 batches = 2368 CTAs = exact 2 waves @ occ 8
//    (148 SMs * 8 CTAs * 2).
//  - loads: LDG.128 (own 4 cols) + LDG.64 (2-col right overlap) per row;
//    rolling 2-row pair sums so each input row is touched once per strip.
//  - stores: sector-aligned paired STG.64 __stcs when (b+orow) is even
//    (output pitch 511 is odd, so parity alternates), else two STG.32.

#define H_IN 1024
#define W_IN 1024
#define H_OUT 511
#define W_OUT 511
#define ROWS_PER_THREAD 14
#define NSTRIPS 37           // ceil(511/14); strip 36 is the tail

__device__ __forceinline__ void emit_row(
    float* __restrict__ orow_p, int oc0, bool aligned8,
    float s0, float q0, float s1, float q1)
{
    const float inv_n = 1.0f / 16.0f;
    const float m0 = s0 * inv_n;
    const float v0 = sqrtf(fmaxf(fmaf(-m0, m0, q0 * inv_n), 0.f));
    if (oc0 + 1 < W_OUT) {
        const float m1 = s1 * inv_n;
        const float v1 = sqrtf(fmaxf(fmaf(-m1, m1, q1 * inv_n), 0.f));
        if (aligned8) {
            // (b + orow) even -> 8B-aligned pair: one full-sector STG.64
            __stcs(reinterpret_cast<float2*>(orow_p + oc0), make_float2(v0, v1));
        } else {
            __stcs(orow_p + oc0, v0);
            __stcs(orow_p + oc0 + 1, v1);
        }
    } else {
        __stcs(orow_p + oc0, v0);   // c == 255: single trailing column
    }
}

template<bool ASC, bool FULL>
__device__ __forceinline__ void run_strip(
    const float* __restrict__ inb, float* __restrict__ outb,
    int r0, int ic, int oc0, bool has2, int b)
{
    float ps0 = 0.f, ps1 = 0.f, pq0 = 0.f, pq1 = 0.f;

    #pragma unroll
    for (int t = 0; t <= ROWS_PER_THREAD; ++t) {
        const int p    = ASC ? t : (ROWS_PER_THREAD - t);   // compile-time affine
        const int irow = 2 * (r0 + p);
        float cs0 = 0.f, cs1 = 0.f, cq0 = 0.f, cq1 = 0.f;

        if (FULL || (irow + 1 < H_IN)) {
            #pragma unroll
            for (int rr = 0; rr < 2; ++rr) {
                const float* rowp = inb + (size_t)(irow + rr) * W_IN + ic;
                const float4 a = *reinterpret_cast<const float4*>(rowp);
                float2 d;
                if (has2) d = *reinterpret_cast<const float2*>(rowp + 4);  // LDG.64
                else      d = make_float2(0.f, 0.f);

                cs0 += a.x + a.y + a.z + a.w;
                cq0 = fmaf(a.x, a.x, fmaf(a.y, a.y, fmaf(a.z, a.z, fmaf(a.w, a.w, cq0))));
                cs1 += a.z + a.w + d.x + d.y;
                cq1 = fmaf(a.z, a.z, fmaf(a.w, a.w, fmaf(d.x, d.x, fmaf(d.y, d.y, cq1))));
            }
        }

        if (t > 0) {
            // ascending: output row uses pairs (p-1, p)  -> orow = r0 + p - 1
            // descending: output row uses pairs (p, p+1) -> orow = r0 + p
            const int orow = ASC ? (r0 + p - 1) : (r0 + p);
            if (FULL || (orow < H_OUT)) {
                float* orow_p = outb + (size_t)orow * W_OUT;
                const bool aligned8 = (((b + orow) & 1) == 0);  // pitch 511 is odd
                emit_row(orow_p, oc0, aligned8,
                         ps0 + cs0, pq0 + cq0, ps1 + cs1, pq1 + cq1);
            }
        }
        ps0 = cs0; ps1 = cs1; pq0 = cq0; pq1 = cq1;
    }
}

__global__ __launch_bounds__(256, 8)
void std_pool_kernel(const float* __restrict__ in, float* __restrict__ out) {
    const int c     = threadIdx.x;                 // col-pair index 0..255
    const int strip = blockIdx.y;
    const int r0    = strip * ROWS_PER_THREAD;
    const int b     = blockIdx.z;

    const float* __restrict__ inb  = in  + (size_t)b * H_IN * W_IN;
    float* __restrict__       outb = out + (size_t)b * H_OUT * W_OUT;

    const int  ic   = 4 * c;                 // first input col
    const bool has2 = (ic + 5) < W_IN;       // float2 at rowp+4 in-bounds (c < 255)
    const int  oc0  = 2 * c;

    const bool full = (strip != NSTRIPS - 1);   // only the last strip needs guards
    if ((strip & 1) == 0) {
        if (full) run_strip<true,  true >(inb, outb, r0, ic, oc0, has2, b);
        else      run_strip<true,  false>(inb, outb, r0, ic, oc0, has2, b);
    } else {
        if (full) run_strip<false, true >(inb, outb, r0, ic, oc0, has2, b);
        else      run_strip<false, false>(inb, outb, r0, ic, oc0, has2, b);
    }
}

extern "C" void kernel_launch(void* const* d_in, const int* in_sizes, int n_in,
                              void* d_out, int out_size) {
    const float* in = (const float*)d_in[0];
    float* out = (float*)d_out;
    (void)in_sizes; (void)n_in; (void)out_size;

    // 256 col-pair threads cover 511 output cols; 37 strips of 14 rows; 64 batches.
    // 37*64 = 2368 CTAs = exactly 2 waves at 8 CTAs/SM x 148 SMs.
    dim3 block(256, 1, 1);
    dim3 grid(1, NSTRIPS, 64);
    std_pool_kernel<<<grid, block>>>(in, out);
}

// round 17
// speedup vs baseline: 1.0145x; 1.0023x over previous
#include <cuda_runtime.h>
#include <cuda_bf16.h>

// StandardDeviationPooling: 4x4 window, stride 2, VALID.
// Input:  [64, 1024, 1024, 1] fp32   Output: [64, 511*511] fp32
// std = sqrt(max(E[x^2] - E[x]^2, 0)) per window.
//
// FINAL (R14 build, confirmed twice: kernel 50.43/50.69us, 6273/6243 GB/s,
// bench 55.42/55.39us, rel_err 5.4e-8). Session-converged optimum:
//  - DRAM traffic ~316 MB = the analytic floor (256 MB in + 67 MB out, each
//    byte once). Boustrophedon strips make strip-boundary re-reads L2 hits:
//    adjacent strips touch shared rows at the same execution phase.
//  - BW 6.24-6.27 TB/s = the measured ceiling for this 79%R/21%W mixed
//    stream on GB300 (DRAM read/write turnaround bound, not LTS/LSU bound).
//  - compile-time strip direction + FULL/TAIL guard specialization:
//    guard-free unrolled body for 36 of 37 strips.
//  - RPT=14 -> 37 strips * 64 batches = 2368 CTAs = exactly 2 waves at
//    8 CTAs/SM x 148 SMs (no wave-tail quantization).
//  - loads: LDG.128 (own 4 cols) + LDG.64 (2-col right overlap) per input
//    row; rolling 2-row pair sums -> each input row touched once per strip.
//  - stores: sector-aligned paired STG.64 __stcs when (b+orow) even
//    (pitch 511 is odd so parity alternates), else two STG.32; streaming
//    hint keeps L2 for the input overlap working set.
// Measured-dead axes: occupancy (R6), L1/LSU (R5/R12), MLP batching (R8),
// hand-rolled epilogue math (R15, regressed). Do not re-touch without SASS.

#define H_IN 1024
#define W_IN 1024
#define H_OUT 511
#define W_OUT 511
#define ROWS_PER_THREAD 14
#define NSTRIPS 37           // ceil(511/14); strip 36 is the tail

__device__ __forceinline__ void emit_row(
    float* __restrict__ orow_p, int oc0, bool aligned8,
    float s0, float q0, float s1, float q1)
{
    const float inv_n = 1.0f / 16.0f;
    const float m0 = s0 * inv_n;
    const float v0 = sqrtf(fmaxf(fmaf(-m0, m0, q0 * inv_n), 0.f));
    if (oc0 + 1 < W_OUT) {
        const float m1 = s1 * inv_n;
        const float v1 = sqrtf(fmaxf(fmaf(-m1, m1, q1 * inv_n), 0.f));
        if (aligned8) {
            // (b + orow) even -> 8B-aligned pair: one full-sector STG.64
            __stcs(reinterpret_cast<float2*>(orow_p + oc0), make_float2(v0, v1));
        } else {
            __stcs(orow_p + oc0, v0);
            __stcs(orow_p + oc0 + 1, v1);
        }
    } else {
        __stcs(orow_p + oc0, v0);   // c == 255: single trailing column
    }
}

template<bool ASC, bool FULL>
__device__ __forceinline__ void run_strip(
    const float* __restrict__ inb, float* __restrict__ outb,
    int r0, int ic, int oc0, bool has2, int b)
{
    float ps0 = 0.f, ps1 = 0.f, pq0 = 0.f, pq1 = 0.f;

    #pragma unroll
    for (int t = 0; t <= ROWS_PER_THREAD; ++t) {
        const int p    = ASC ? t : (ROWS_PER_THREAD - t);   // compile-time affine
        const int irow = 2 * (r0 + p);
        float cs0 = 0.f, cs1 = 0.f, cq0 = 0.f, cq1 = 0.f;

        if (FULL || (irow + 1 < H_IN)) {
            #pragma unroll
            for (int rr = 0; rr < 2; ++rr) {
                const float* rowp = inb + (size_t)(irow + rr) * W_IN + ic;
                const float4 a = *reinterpret_cast<const float4*>(rowp);
                float2 d;
                if (has2) d = *reinterpret_cast<const float2*>(rowp + 4);  // LDG.64
                else      d = make_float2(0.f, 0.f);

                cs0 += a.x + a.y + a.z + a.w;
                cq0 = fmaf(a.x, a.x, fmaf(a.y, a.y, fmaf(a.z, a.z, fmaf(a.w, a.w, cq0))));
                cs1 += a.z + a.w + d.x + d.y;
                cq1 = fmaf(a.z, a.z, fmaf(a.w, a.w, fmaf(d.x, d.x, fmaf(d.y, d.y, cq1))));
            }
        }

        if (t > 0) {
            // ascending: output row uses pairs (p-1, p)  -> orow = r0 + p - 1
            // descending: output row uses pairs (p, p+1) -> orow = r0 + p
            const int orow = ASC ? (r0 + p - 1) : (r0 + p);
            if (FULL || (orow < H_OUT)) {
                float* orow_p = outb + (size_t)orow * W_OUT;
                const bool aligned8 = (((b + orow) & 1) == 0);  // pitch 511 is odd
                emit_row(orow_p, oc0, aligned8,
                         ps0 + cs0, pq0 + cq0, ps1 + cs1, pq1 + cq1);
            }
        }
        ps0 = cs0; ps1 = cs1; pq0 = cq0; pq1 = cq1;
    }
}

__global__ __launch_bounds__(256, 8)
void std_pool_kernel(const float* __restrict__ in, float* __restrict__ out) {
    const int c     = threadIdx.x;                 // col-pair index 0..255
    const int strip = blockIdx.y;
    const int r0    = strip * ROWS_PER_THREAD;
    const int b     = blockIdx.z;

    const float* __restrict__ inb  = in  + (size_t)b * H_IN * W_IN;
    float* __restrict__       outb = out + (size_t)b * H_OUT * W_OUT;

    const int  ic   = 4 * c;                 // first input col
    const bool has2 = (ic + 5) < W_IN;       // float2 at rowp+4 in-bounds (c < 255)
    const int  oc0  = 2 * c;

    const bool full = (strip != NSTRIPS - 1);   // only the last strip needs guards
    if ((strip & 1) == 0) {
        if (full) run_strip<true,  true >(inb, outb, r0, ic, oc0, has2, b);
        else      run_strip<true,  false>(inb, outb, r0, ic, oc0, has2, b);
    } else {
        if (full) run_strip<false, true >(inb, outb, r0, ic, oc0, has2, b);
        else      run_strip<false, false>(inb, outb, r0, ic, oc0, has2, b);
    }
}

extern "C" void kernel_launch(void* const* d_in, const int* in_sizes, int n_in,
                              void* d_out, int out_size) {
    const float* in = (const float*)d_in[0];
    float* out = (float*)d_out;
    (void)in_sizes; (void)n_in; (void)out_size;

    // 256 col-pair threads cover 511 output cols; 37 strips of 14 rows; 64 batches.
    // 37*64 = 2368 CTAs = exactly 2 waves at 8 CTAs/SM x 148 SMs.
    dim3 block(256, 1, 1);
    dim3 grid(1, NSTRIPS, 64);
    std_pool_kernel<<<grid, block>>>(in, out);
}